// round 15
// baseline (speedup 1.0000x reference)
#include <cuda_runtime.h>

#define HID  128
#define NIN  64
#define NOUT 64
#define NB   256
#define NS   4096

// xp[b][s][j] = x@Wx + bh + bx (bias folded), float. 512 MB.
__device__ float g_xp[NB][NS][HID];
// hs[b][s][j], float. 512 MB.
__device__ float g_hs[NB][NS][HID];

// ---------------------------------------------------------------------------
// Kernel 1 (slim, ~48 regs): xp = x@Wx + bh + bx for 32-step tiles.
// 256 threads: j = t>>1 (0..127), ih = t&1 (i-half). wxc[32] regs; one
// shfl_xor(1) reduce. Skewed x tile (pad 4 per 32) -> ih halves on distinct
// banks, float4-aligned.
// ---------------------------------------------------------------------------
__global__ void __launch_bounds__(256) xp_kernel(
    const float* __restrict__ x,  const float* __restrict__ Wx,
    const float* __restrict__ bh, const float* __restrict__ bx, int s_base)
{
    __shared__ __align__(16) float xt[32][72];   // idx = i + 4*(i>>5)

    const int t  = threadIdx.x;
    const int j  = t >> 1;
    const int ih = t & 1;
    const int b  = blockIdx.y;
    const int s0 = s_base + blockIdx.x * 32;

    float wxc[32];
#pragma unroll
    for (int m = 0; m < 32; m++)
        wxc[m] = Wx[(ih * 32 + m) * HID + j];
    const float bsum = (ih == 0) ? (bh[j] + bx[j]) : 0.f;

    // Tile load: 32 s x 64 i = 512 float4, 2 per thread, coalesced.
#pragma unroll
    for (int q = 0; q < 2; q++) {
        int idx4 = t + q * 256;
        int s  = idx4 >> 4;
        int i4 = (idx4 & 15) * 4;
        float4 v = *(const float4*)&x[((long long)b * NS + s0 + s) * NIN + i4];
        *(float4*)&xt[s][i4 + 4 * (i4 >> 5)] = v;
    }
    __syncthreads();

#pragma unroll 2
    for (int s = 0; s < 32; s++) {
        const float* xr = &xt[s][ih * 36];
        float a0 = bsum, a1 = 0.f, a2 = 0.f, a3 = 0.f;
#pragma unroll
        for (int m = 0; m < 32; m += 4) {
            float4 xv = *(const float4*)(xr + m);
            a0 = fmaf(wxc[m],     xv.x, a0);
            a1 = fmaf(wxc[m + 1], xv.y, a1);
            a2 = fmaf(wxc[m + 2], xv.z, a2);
            a3 = fmaf(wxc[m + 3], xv.w, a3);
        }
        float r = (a0 + a1) + (a2 + a3);
        r += __shfl_xor_sync(0xffffffffu, r, 1);
        if (ih == 0)
            g_xp[b][s0 + s][j] = r;
    }
}

// ---------------------------------------------------------------------------
// Kernel 2: recurrence chunk [s0,s1), s0/s1 % 4 == 0.  (R13, unchanged)
// ---------------------------------------------------------------------------
__global__ void __launch_bounds__(256, 1) rnn_rec_chunk(
    const float* __restrict__ Wh, int s0, int s1)
{
    __shared__ __align__(16) float hbufF[2][2][HID];     // [grp][buf][j]
    __shared__ __align__(16) float xsr[2][2][4][HID];    // [grp][slot][st][j]

    const int tid = threadIdx.x;
    const int g   = tid >> 7;
    const int u   = tid & 127;
    const int b   = blockIdx.x * 2 + g;
    const int bar = g + 1;

    float whc[128];
#pragma unroll
    for (int k = 0; k < 128; k++)
        whc[k] = Wh[k * HID + u];

    const int st_ld = u >> 5;
    const int j4    = (u & 31) * 4;

    const int B0 = s0 >> 2, B1 = s1 >> 2;

    hbufF[g][0][u] = (s0 == 0) ? 0.f : g_hs[b][s0 - 1][u];
    *(float4*)&xsr[g][B0 & 1][st_ld][j4] =
        *(const float4*)&g_xp[b][4 * B0 + st_ld][j4];
    float4 xr = make_float4(0.f, 0.f, 0.f, 0.f);
    if (4 * (B0 + 1) < NS)
        xr = *(const float4*)&g_xp[b][4 * (B0 + 1) + st_ld][j4];
    asm volatile("bar.sync %0, 128;" :: "r"(bar) : "memory");

    for (int bc = B0; bc < B1; bc++) {
        if (4 * (bc + 1) < NS)
            *(float4*)&xsr[g][(bc + 1) & 1][st_ld][j4] = xr;
        if (4 * (bc + 2) < NS)
            xr = *(const float4*)&g_xp[b][4 * (bc + 2) + st_ld][j4];

#pragma unroll
        for (int st = 0; st < 4; st++) {
            const int cur = st & 1, nxt = cur ^ 1;

            float a0 = xsr[g][bc & 1][st][u];
            float a1 = 0.f, a2 = 0.f, a3 = 0.f;
            const float* hb = hbufF[g][cur];
#pragma unroll
            for (int m = 0; m < 128; m += 4) {
                float4 hv = *(const float4*)(hb + m);
                a0 = fmaf(whc[m],     hv.x, a0);
                a1 = fmaf(whc[m + 1], hv.y, a1);
                a2 = fmaf(whc[m + 2], hv.z, a2);
                a3 = fmaf(whc[m + 3], hv.w, a3);
            }
            float h = fmaxf((a0 + a1) + (a2 + a3), 0.f);
            hbufF[g][nxt][u] = h;
            g_hs[b][4 * bc + st][u] = h;
            asm volatile("bar.sync %0, 128;" :: "r"(bar) : "memory");
        }
    }
}

// ---------------------------------------------------------------------------
// Kernel 3 (slim, ~48 regs): out[b][s][o] = hs@Wy + by for 32-step tiles.
// 256 threads: o = t>>2 (0..63), kq = t&3. wyc[32] regs; shfl_xor(1),(2).
// Skewed hs tile (pad 4 per 32): kq quarters on banks 0/4/8/12, f4-aligned.
// ---------------------------------------------------------------------------
__global__ void __launch_bounds__(256) rnn_output(
    const float* __restrict__ Wy, const float* __restrict__ by,
    float* __restrict__ out, int s_base)
{
    __shared__ __align__(16) float hst[32][144];   // idx = jj + 4*(jj>>5)

    const int t  = threadIdx.x;
    const int o  = t >> 2;
    const int kq = t & 3;
    const int b  = blockIdx.y;
    const int s0 = s_base + blockIdx.x * 32;

    float wyc[32];
#pragma unroll
    for (int k = 0; k < 32; k++)
        wyc[k] = Wy[(kq * 32 + k) * NOUT + o];
    const float byv = (kq == 0) ? by[o] : 0.f;

    // Tile load: 32 s x 128 j = 1024 float4, 4 per thread, coalesced.
#pragma unroll
    for (int q = 0; q < 4; q++) {
        int idx4 = t + q * 256;
        int s  = idx4 >> 5;
        int jj = (idx4 & 31) * 4;
        float4 v = *(const float4*)&g_hs[b][s0 + s][jj];
        *(float4*)&hst[s][jj + 4 * (jj >> 5)] = v;
    }
    __syncthreads();

#pragma unroll 2
    for (int s = 0; s < 32; s++) {
        const float* hb = &hst[s][kq * 36];
        float a0 = byv, a1 = 0.f, a2 = 0.f, a3 = 0.f;
#pragma unroll
        for (int m = 0; m < 32; m += 4) {
            float4 hv = *(const float4*)(hb + m);
            a0 = fmaf(wyc[m],     hv.x, a0);
            a1 = fmaf(wyc[m + 1], hv.y, a1);
            a2 = fmaf(wyc[m + 2], hv.z, a2);
            a3 = fmaf(wyc[m + 3], hv.w, a3);
        }
        float r = (a0 + a1) + (a2 + a3);
        r += __shfl_xor_sync(0xffffffffu, r, 1);
        r += __shfl_xor_sync(0xffffffffu, r, 2);
        if (kq == 0)
            out[((long long)b * NS + s0 + s) * NOUT + o] = r;
    }
}

// ---------------------------------------------------------------------------
// 4-chunk two-stream pipeline (chunks of 1024 steps, 32 tiles each):
//   main: xp0 | rec0 | rec1 | rec2 | rec3 | out3
//   s1:          xp1, xp2, xp3, out0, out1, out2
// Deps: rec_k <- xp_k; out_k <- rec_k; out3 <- all outs.
// ---------------------------------------------------------------------------
extern "C" void kernel_launch(void* const* d_in, const int* in_sizes, int n_in,
                              void* d_out, int out_size)
{
    const float* x  = (const float*)d_in[0];
    const float* Wh = (const float*)d_in[1];
    const float* bh = (const float*)d_in[2];
    const float* Wx = (const float*)d_in[3];
    const float* bx = (const float*)d_in[4];
    const float* Wy = (const float*)d_in[5];
    const float* by = (const float*)d_in[6];
    float* out = (float*)d_out;

    static cudaStream_t s1 = nullptr;
    static cudaEvent_t ev0, evX1, evX2, evX3, evR0, evR1, evR2, evOut;
    if (s1 == nullptr) {
        cudaStreamCreateWithFlags(&s1, cudaStreamNonBlocking);
        cudaEventCreateWithFlags(&ev0,   cudaEventDisableTiming);
        cudaEventCreateWithFlags(&evX1,  cudaEventDisableTiming);
        cudaEventCreateWithFlags(&evX2,  cudaEventDisableTiming);
        cudaEventCreateWithFlags(&evX3,  cudaEventDisableTiming);
        cudaEventCreateWithFlags(&evR0,  cudaEventDisableTiming);
        cudaEventCreateWithFlags(&evR1,  cudaEventDisableTiming);
        cudaEventCreateWithFlags(&evR2,  cudaEventDisableTiming);
        cudaEventCreateWithFlags(&evOut, cudaEventDisableTiming);
    }

    // xp0 serial on main
    xp_kernel<<<dim3(32, NB), 256>>>(x, Wx, bh, bx, 0);
    cudaEventRecord(ev0, 0);

    // xp1..xp3 on s1
    cudaStreamWaitEvent(s1, ev0, 0);
    xp_kernel<<<dim3(32, NB), 256, 0, s1>>>(x, Wx, bh, bx, 1024);
    cudaEventRecord(evX1, s1);
    xp_kernel<<<dim3(32, NB), 256, 0, s1>>>(x, Wx, bh, bx, 2048);
    cudaEventRecord(evX2, s1);
    xp_kernel<<<dim3(32, NB), 256, 0, s1>>>(x, Wx, bh, bx, 3072);
    cudaEventRecord(evX3, s1);

    // rec chain on main, gated by xp events
    rnn_rec_chunk<<<NB / 2, 256>>>(Wh, 0, 1024);
    cudaEventRecord(evR0, 0);
    cudaStreamWaitEvent(0, evX1, 0);
    rnn_rec_chunk<<<NB / 2, 256>>>(Wh, 1024, 2048);
    cudaEventRecord(evR1, 0);
    cudaStreamWaitEvent(0, evX2, 0);
    rnn_rec_chunk<<<NB / 2, 256>>>(Wh, 2048, 3072);
    cudaEventRecord(evR2, 0);
    cudaStreamWaitEvent(0, evX3, 0);
    rnn_rec_chunk<<<NB / 2, 256>>>(Wh, 3072, 4096);

    // out0..out2 on s1, gated by rec events
    cudaStreamWaitEvent(s1, evR0, 0);
    rnn_output<<<dim3(32, NB), 256, 0, s1>>>(Wy, by, out, 0);
    cudaStreamWaitEvent(s1, evR1, 0);
    rnn_output<<<dim3(32, NB), 256, 0, s1>>>(Wy, by, out, 1024);
    cudaStreamWaitEvent(s1, evR2, 0);
    rnn_output<<<dim3(32, NB), 256, 0, s1>>>(Wy, by, out, 2048);
    cudaEventRecord(evOut, s1);

    // join + out3 on main
    cudaStreamWaitEvent(0, evOut, 0);
    rnn_output<<<dim3(32, NB), 256>>>(Wy, by, out, 3072);
}